// round 14
// baseline (speedup 1.0000x reference)
#include <cuda_runtime.h>
#include <cuda_bf16.h>
#include <math.h>
#include <stdint.h>

// ---------------------------------------------------------------------------
// GAT (4x32 heads) + autoencoder head. R14 = R13 +
//  (1) chunked gather->tail software pipeline across 4 node ranges
//      (gather: L2-bound; tail: tensor-bound -> complementary overlap)
//  (2) self-loop moved into k_gather (k1_gat no longer writes agg/denom).
// ---------------------------------------------------------------------------

#define MAXN 50176                    // 196 * 256
#define MAXE 800000
#define TM 64
#define KS2 264
#define SM_B (TM * KS2 * 2)
#define SMEM_TOT (SM_B + 128 * KS2 * 2)
#define NCHUNK 4
#define ROWS_CHUNK 12544              // 196 tiles * 64 rows

__device__ __align__(16) float g_h[MAXN * 128];
__device__ __align__(16) float g_agg[MAXN * 128];
__device__ __align__(16) float g_asrc[MAXN * 4];
__device__ __align__(16) float g_adst[MAXN * 4];
__device__ __align__(16) float g_denom[MAXN * 4];
__device__ __align__(16) float g_Wcd[128 * 128];
__device__ __align__(16) float g_bcd[128];
__device__ __align__(16) __nv_bfloat16 g_BgT[128 * KS2];
__device__ __align__(16) __nv_bfloat16 g_BcdT[128 * KS2];
__device__ __align__(16) __nv_bfloat16 g_BoT[128 * KS2];
// CSR scratch
__device__ int g_cnt[MAXN];
__device__ int g_start[MAXN + 1];
__device__ int g_blk[256];
__device__ int g_srcs[MAXE];

__device__ __forceinline__ float lrelu(float v) { return v > 0.f ? v : 0.2f * v; }
__device__ __forceinline__ float elu(float v)   { return v > 0.f ? v : (expf(v) - 1.f); }
__device__ __forceinline__ float sel_head(float4 v, int lane) {
    return lane < 16 ? (lane < 8 ? v.x : v.y) : (lane < 24 ? v.z : v.w);
}

__device__ __forceinline__ uint32_t smem_u32(const void* p) {
    uint32_t a;
    asm("{ .reg .u64 t; cvta.to.shared.u64 t, %1; cvt.u32.u64 %0, t; }" : "=r"(a) : "l"(p));
    return a;
}

#define LDSM_X4(r0, r1, r2, r3, addr)                                         \
    asm volatile("ldmatrix.sync.aligned.m8n8.x4.shared.b16 {%0,%1,%2,%3}, [%4];" \
                 : "=r"(r0), "=r"(r1), "=r"(r2), "=r"(r3) : "r"(addr))
#define MMA(c, a0, a1, a2, a3, b0, b1)                                        \
    asm volatile("mma.sync.aligned.m16n8k16.row.col.f32.bf16.bf16.f32 "       \
                 "{%0,%1,%2,%3}, {%4,%5,%6,%7}, {%8,%9}, {%0,%1,%2,%3};"      \
                 : "+f"((c)[0]), "+f"((c)[1]), "+f"((c)[2]), "+f"((c)[3])     \
                 : "r"(a0), "r"(a1), "r"(a2), "r"(a3), "r"(b0), "r"(b1))

__device__ __forceinline__ void split2(char* base, int r, int k, float a, float b) {
    __nv_bfloat16 ha = __float2bfloat16(a), hb = __float2bfloat16(b);
    __nv_bfloat162 hp; hp.x = ha; hp.y = hb;
    __nv_bfloat162 lp;
    lp.x = __float2bfloat16(a - __bfloat162float(ha));
    lp.y = __float2bfloat16(b - __bfloat162float(hb));
    *(__nv_bfloat162*)(base + (size_t)(r * KS2 + k) * 2)       = hp;
    *(__nv_bfloat162*)(base + (size_t)(r * KS2 + k + 128) * 2) = lp;
}

__device__ __forceinline__ void gemm3(uint32_t sbA, uint32_t sbB,
                                      int wm, int wn, int lane, float acc[8][4]) {
    uint32_t arow = (uint32_t)(wm * 16 + (lane & 15));
    uint32_t aka  = (uint32_t)((lane >> 4) * 8);
    uint32_t brow = (uint32_t)(wn * 64 + ((lane >> 4) << 3) + (lane & 7));
    uint32_t bka  = (uint32_t)(((lane >> 3) & 1) * 8);
    #pragma unroll
    for (int p = 0; p < 3; p++) {
        int aOff = (p == 1) ? 128 : 0;
        int bOff = (p == 2) ? 128 : 0;
        uint32_t abase = sbA + (arow * KS2 + aOff + aka) * 2;
        uint32_t bbase = sbB + (brow * KS2 + bOff + bka) * 2;
        #pragma unroll
        for (int kc = 0; kc < 8; kc++) {
            uint32_t a0, a1, a2, a3;
            LDSM_X4(a0, a1, a2, a3, abase + kc * 32);
            #pragma unroll
            for (int np = 0; np < 4; np++) {
                uint32_t b0, b1, b2, b3;
                LDSM_X4(b0, b1, b2, b3, bbase + np * (16 * KS2 * 2) + kc * 32);
                MMA(acc[2 * np],     a0, a1, a2, a3, b0, b1);
                MMA(acc[2 * np + 1], a0, a1, a2, a3, b2, b3);
            }
        }
    }
}

__device__ __forceinline__ void copyB(char* smem, const __nv_bfloat16* src, int tid) {
    const float4* s4 = (const float4*)src;
    float4* d4 = (float4*)(smem + SM_B);
    #pragma unroll 4
    for (int i = tid; i < 128 * KS2 / 8; i += 256) d4[i] = s4[i];
}

// ------------------------------- CSR build ---------------------------------
__global__ void k_zero() {
    int i = blockIdx.x * 256 + threadIdx.x;
    if (i < MAXN) g_cnt[i] = 0;
}
__global__ void k_hist(const int* __restrict__ ei, int E) {
    int e = blockIdx.x * 256 + threadIdx.x;
    if (e < E) atomicAdd(&g_cnt[ei[E + e]], 1);
}
__global__ void k_scanA() {
    __shared__ int s[256];
    int i = blockIdx.x * 256 + threadIdx.x;
    s[threadIdx.x] = g_cnt[i];
    __syncthreads();
    for (int off = 128; off > 0; off >>= 1) {
        if (threadIdx.x < off) s[threadIdx.x] += s[threadIdx.x + off];
        __syncthreads();
    }
    if (threadIdx.x == 0) g_blk[blockIdx.x] = s[0];
}
__global__ void k_scanC(int nblk) {
    __shared__ int bs[256];
    __shared__ int s[256];
    int t = threadIdx.x;
    bs[t] = (t < nblk) ? g_blk[t] : 0;
    __syncthreads();
    for (int off = 1; off < 256; off <<= 1) {
        int v = (t >= off) ? bs[t - off] : 0;
        __syncthreads();
        bs[t] += v;
        __syncthreads();
    }
    int blk_off = (blockIdx.x == 0) ? 0 : bs[blockIdx.x - 1];

    int i = blockIdx.x * 256 + t;
    int c = g_cnt[i];
    s[t] = c;
    __syncthreads();
    for (int off = 1; off < 256; off <<= 1) {
        int v = (t >= off) ? s[t - off] : 0;
        __syncthreads();
        s[t] += v;
        __syncthreads();
    }
    g_start[i] = blk_off + s[t] - c;
    g_cnt[i] = 0;
    if (i == MAXN - 1) g_start[MAXN] = blk_off + s[t];
}
__global__ void k_fill(const int* __restrict__ ei, int E) {
    int e = blockIdx.x * 256 + threadIdx.x;
    if (e >= E) return;
    int d = ei[E + e];
    int pos = atomicAdd(&g_cnt[d], 1);
    g_srcs[g_start[d] + pos] = ei[e];
}

// ---------------------------------------------------------------------------
__global__ void k_prep(const float* __restrict__ We, const float* __restrict__ Wd,
                       const float* __restrict__ be, const float* __restrict__ bd) {
    int r = blockIdx.x, j = threadIdx.x;
    if (r < 128) {
        float a = 0.f;
        #pragma unroll
        for (int k = 0; k < 64; k++) a += We[r * 64 + k] * Wd[k * 128 + j];
        g_Wcd[r * 128 + j] = a;
    } else {
        float a = bd[j];
        #pragma unroll
        for (int k = 0; k < 64; k++) a += be[k] * Wd[k * 128 + j];
        g_bcd[j] = a;
    }
}

__global__ void k_prep2(const float* __restrict__ Wg, const float* __restrict__ Wo) {
    int n = blockIdx.x, k = threadIdx.x;
    float v;
    __nv_bfloat16 hb;
    v = Wg[k * 128 + n]; hb = __float2bfloat16(v);
    g_BgT[n * KS2 + k] = hb;
    g_BgT[n * KS2 + 128 + k] = __float2bfloat16(v - __bfloat162float(hb));
    v = g_Wcd[k * 128 + n]; hb = __float2bfloat16(v);
    g_BcdT[n * KS2 + k] = hb;
    g_BcdT[n * KS2 + 128 + k] = __float2bfloat16(v - __bfloat162float(hb));
    v = Wo[k * 128 + n]; hb = __float2bfloat16(v);
    g_BoT[n * KS2 + k] = hb;
    g_BoT[n * KS2 + 128 + k] = __float2bfloat16(v - __bfloat162float(hb));
}

// ---------------------------------------------------------------------------
// k1_gat: h = x @ W_gat (tensor); epilogue: h + logits ONLY (self-loop term
// moved to k_gather).
// ---------------------------------------------------------------------------
__global__ __launch_bounds__(256, 2) void k1_gat(
    const float* __restrict__ x, const float* __restrict__ att_s,
    const float* __restrict__ att_d, int N) {
    extern __shared__ char smem[];
    uint32_t sb = smem_u32(smem);
    int tid = threadIdx.x, wid = tid >> 5, lane = tid & 31;
    int wm = wid >> 1, wn = wid & 1;
    int row0 = blockIdx.x * TM;

    const float4* x4 = (const float4*)x;
    for (int i = tid; i < TM * 32; i += 256) {
        int r = i >> 5, c4 = i & 31, gr = row0 + r;
        float4 v = (gr < N) ? x4[(size_t)gr * 32 + c4] : make_float4(0.f, 0.f, 0.f, 0.f);
        split2(smem, r, c4 * 4, v.x, v.y);
        split2(smem, r, c4 * 4 + 2, v.z, v.w);
    }
    copyB(smem, g_BgT, tid);
    __syncthreads();

    float acc[8][4];
    #pragma unroll
    for (int i = 0; i < 8; i++)
        #pragma unroll
        for (int j = 0; j < 4; j++) acc[i][j] = 0.f;
    gemm3(sb, sb + SM_B, wm, wn, lane, acc);

    int g = lane >> 2, q = lane & 3;
    int grA = row0 + wm * 16 + g;
    int grB = grA + 8;
    #pragma unroll
    for (int hl = 0; hl < 2; hl++) {
        int hh = wn * 2 + hl;
        float sAs = 0.f, sAd = 0.f, sBs = 0.f, sBd = 0.f;
        #pragma unroll
        for (int t = 0; t < 4; t++) {
            int nt = hl * 4 + t;
            int c0 = wn * 64 + nt * 8 + q * 2;
            float w0s = __ldg(&att_s[c0]), w1s = __ldg(&att_s[c0 + 1]);
            float w0d = __ldg(&att_d[c0]), w1d = __ldg(&att_d[c0 + 1]);
            sAs += acc[nt][0] * w0s + acc[nt][1] * w1s;
            sAd += acc[nt][0] * w0d + acc[nt][1] * w1d;
            sBs += acc[nt][2] * w0s + acc[nt][3] * w1s;
            sBd += acc[nt][2] * w0d + acc[nt][3] * w1d;
        }
        #pragma unroll
        for (int off = 1; off <= 2; off <<= 1) {
            sAs += __shfl_xor_sync(0xffffffffu, sAs, off);
            sAd += __shfl_xor_sync(0xffffffffu, sAd, off);
            sBs += __shfl_xor_sync(0xffffffffu, sBs, off);
            sBd += __shfl_xor_sync(0xffffffffu, sBd, off);
        }
        if (q == 0) {
            if (grA < N) { g_asrc[grA * 4 + hh] = sAs; g_adst[grA * 4 + hh] = sAd; }
            if (grB < N) { g_asrc[grB * 4 + hh] = sBs; g_adst[grB * 4 + hh] = sBd; }
        }
    }
    #pragma unroll
    for (int nt = 0; nt < 8; nt++) {
        int c0 = wn * 64 + nt * 8 + q * 2;
        if (grA < N)
            *(float2*)&g_h[(size_t)grA * 128 + c0] = make_float2(acc[nt][0], acc[nt][1]);
        if (grB < N)
            *(float2*)&g_h[(size_t)grB * 128 + c0] = make_float2(acc[nt][2], acc[nt][3]);
    }
}

// ---------------------------------------------------------------------------
// k_gather: one warp per dst node in [d0, d0+cnt). Self-loop computed here.
// 2-way pipelined CSR walk, register accumulation, single store. No atomics.
// ---------------------------------------------------------------------------
__global__ __launch_bounds__(256) void k_gather(int N, int d0, int cnt) {
    int d = d0 + blockIdx.x * 8 + (threadIdx.x >> 5);
    if (d >= d0 + cnt || d >= N) return;
    int lane = threadIdx.x & 31;

    float4 as_d = ((const float4*)g_asrc)[d];
    float4 ad4 = ((const float4*)g_adst)[d];
    float adv = sel_head(ad4, lane);
    float es = sel_head(as_d, lane) + adv;            // self-loop logit
    float p = expf(es > 0.f ? es : 0.2f * es);

    float4 acc = ((const float4*)g_h)[(size_t)d * 32 + lane];
    acc.x *= p; acc.y *= p; acc.z *= p; acc.w *= p;
    float den = p;

    int beg = g_start[d], end = g_start[d + 1];
    int i = beg;
    for (; i + 1 < end; i += 2) {
        int s0 = g_srcs[i], s1 = g_srcs[i + 1];
        float4 as0 = ((const float4*)g_asrc)[s0];
        float4 as1 = ((const float4*)g_asrc)[s1];
        float4 h0 = ((const float4*)g_h)[(size_t)s0 * 32 + lane];
        float4 h1 = ((const float4*)g_h)[(size_t)s1 * 32 + lane];
        float e0 = sel_head(as0, lane) + adv;
        float e1 = sel_head(as1, lane) + adv;
        float p0 = expf(e0 > 0.f ? e0 : 0.2f * e0);
        float p1 = expf(e1 > 0.f ? e1 : 0.2f * e1);
        den += p0 + p1;
        acc.x = fmaf(p0, h0.x, fmaf(p1, h1.x, acc.x));
        acc.y = fmaf(p0, h0.y, fmaf(p1, h1.y, acc.y));
        acc.z = fmaf(p0, h0.z, fmaf(p1, h1.z, acc.z));
        acc.w = fmaf(p0, h0.w, fmaf(p1, h1.w, acc.w));
    }
    if (i < end) {
        int s0 = g_srcs[i];
        float4 as0 = ((const float4*)g_asrc)[s0];
        float4 h0 = ((const float4*)g_h)[(size_t)s0 * 32 + lane];
        float e0 = sel_head(as0, lane) + adv;
        float p0 = expf(e0 > 0.f ? e0 : 0.2f * e0);
        den += p0;
        acc.x = fmaf(p0, h0.x, acc.x);
        acc.y = fmaf(p0, h0.y, acc.y);
        acc.z = fmaf(p0, h0.z, acc.z);
        acc.w = fmaf(p0, h0.w, acc.w);
    }

    ((float4*)g_agg)[(size_t)d * 32 + lane] = acc;
    if ((lane & 7) == 0)
        g_denom[d * 4 + (lane >> 3)] = den;
}

// ---------------------------------------------------------------------------
// k_tail: rows [row_base + blockIdx.x*TM ...]. x1=elu(agg/den+bg); GEMM1
// @Wcd; x2=elu(+bcd) -> A; B<-Wo^T; GEMM2; out.
// ---------------------------------------------------------------------------
__global__ __launch_bounds__(256, 2) void k_tail(
    const float* __restrict__ bg, const float* __restrict__ bo,
    float* __restrict__ out, int N, int row_base) {
    extern __shared__ char smem[];
    uint32_t sb = smem_u32(smem);
    int tid = threadIdx.x, wid = tid >> 5, lane = tid & 31;
    int wm = wid >> 1, wn = wid & 1;
    int row0 = row_base + blockIdx.x * TM;

    const float4* agg4 = (const float4*)g_agg;
    const float4* bg4 = (const float4*)bg;
    for (int i = tid; i < TM * 32; i += 256) {
        int r = i >> 5, c4 = i & 31, gr = row0 + r;
        float4 v = make_float4(0.f, 0.f, 0.f, 0.f);
        if (gr < N) {
            float4 a = agg4[(size_t)gr * 32 + c4];
            float inv = 1.f / (g_denom[gr * 4 + (c4 >> 3)] + 1e-16f);
            float4 b = bg4[c4];
            v.x = elu(a.x * inv + b.x); v.y = elu(a.y * inv + b.y);
            v.z = elu(a.z * inv + b.z); v.w = elu(a.w * inv + b.w);
        }
        split2(smem, r, c4 * 4, v.x, v.y);
        split2(smem, r, c4 * 4 + 2, v.z, v.w);
    }
    copyB(smem, g_BcdT, tid);
    __syncthreads();

    float acc[8][4];
    #pragma unroll
    for (int i = 0; i < 8; i++)
        #pragma unroll
        for (int j = 0; j < 4; j++) acc[i][j] = 0.f;
    gemm3(sb, sb + SM_B, wm, wn, lane, acc);
    __syncthreads();

    int g = lane >> 2, q = lane & 3;
    int lrA = wm * 16 + g, lrB = lrA + 8;
    #pragma unroll
    for (int nt = 0; nt < 8; nt++) {
        int c0 = wn * 64 + nt * 8 + q * 2;
        float bc0 = g_bcd[c0], bc1 = g_bcd[c0 + 1];
        split2(smem, lrA, c0, elu(acc[nt][0] + bc0), elu(acc[nt][1] + bc1));
        split2(smem, lrB, c0, elu(acc[nt][2] + bc0), elu(acc[nt][3] + bc1));
    }
    copyB(smem, g_BoT, tid);
    __syncthreads();

    #pragma unroll
    for (int i = 0; i < 8; i++)
        #pragma unroll
        for (int j = 0; j < 4; j++) acc[i][j] = 0.f;
    gemm3(sb, sb + SM_B, wm, wn, lane, acc);

    int grA = row0 + lrA, grB = row0 + lrB;
    #pragma unroll
    for (int nt = 0; nt < 8; nt++) {
        int c0 = wn * 64 + nt * 8 + q * 2;
        float b0 = __ldg(&bo[c0]), b1 = __ldg(&bo[c0 + 1]);
        if (grA < N)
            *(float2*)&out[(size_t)grA * 128 + c0] =
                make_float2(acc[nt][0] + b0, acc[nt][1] + b1);
        if (grB < N)
            *(float2*)&out[(size_t)grB * 128 + c0] =
                make_float2(acc[nt][2] + b0, acc[nt][3] + b1);
    }
}

// ---------------------------------------------------------------------------

extern "C" void kernel_launch(void* const* d_in, const int* in_sizes, int n_in,
                              void* d_out, int out_size) {
    const float* x     = (const float*)d_in[0];
    const int*   ei    = (const int*)d_in[1];
    const float* Wg    = (const float*)d_in[2];
    const float* bg    = (const float*)d_in[3];
    const float* att_s = (const float*)d_in[4];
    const float* att_d = (const float*)d_in[5];
    const float* We    = (const float*)d_in[6];
    const float* be    = (const float*)d_in[7];
    const float* Wd    = (const float*)d_in[8];
    const float* bd    = (const float*)d_in[9];
    const float* Wo    = (const float*)d_in[10];
    const float* bo    = (const float*)d_in[11];
    float* out = (float*)d_out;

    int N = in_sizes[0] / 128;
    int E = in_sizes[1] / 2;

    // One-time resources (no device memory involved).
    static cudaStream_t s2 = nullptr;
    static cudaEvent_t evF = nullptr, evK = nullptr, evG[NCHUNK] = {};
    if (s2 == nullptr) {
        cudaStreamCreateWithFlags(&s2, cudaStreamNonBlocking);
        cudaEventCreateWithFlags(&evF, cudaEventDisableTiming);
        cudaEventCreateWithFlags(&evK, cudaEventDisableTiming);
        for (int c = 0; c < NCHUNK; c++)
            cudaEventCreateWithFlags(&evG[c], cudaEventDisableTiming);
    }

    cudaFuncSetAttribute(k1_gat, cudaFuncAttributeMaxDynamicSharedMemorySize, SMEM_TOT);
    cudaFuncSetAttribute(k_tail, cudaFuncAttributeMaxDynamicSharedMemorySize, SMEM_TOT);

    int nb = (N + TM - 1) / TM;
    int eb = (E + 255) / 256;

    // Fork: CSR build on side stream (depends only on edge_index).
    cudaEventRecord(evF, 0);
    cudaStreamWaitEvent(s2, evF, 0);
    k_zero<<<MAXN / 256, 256, 0, s2>>>();
    k_hist<<<eb, 256, 0, s2>>>(ei, E);
    k_scanA<<<MAXN / 256, 256, 0, s2>>>();
    k_scanC<<<MAXN / 256, 256, 0, s2>>>(MAXN / 256);
    k_fill<<<eb, 256, 0, s2>>>(ei, E);

    // Dense prefix on the captured (default) stream.
    k_prep<<<129, 128>>>(We, Wd, be, bd);
    k_prep2<<<128, 128>>>(Wg, Wo);
    k1_gat<<<nb, 256, SMEM_TOT>>>(x, att_s, att_d, N);
    cudaEventRecord(evK, 0);

    // Pipelined gather (s2) / tail (stream 0) over node chunks.
    cudaStreamWaitEvent(s2, evK, 0);        // gather needs h/logits + CSR
    for (int c = 0; c < NCHUNK; c++) {
        int r0 = c * ROWS_CHUNK;
        if (r0 >= N) { cudaEventRecord(evG[c], s2); continue; }
        int rows = (N - r0 < ROWS_CHUNK) ? (N - r0) : ROWS_CHUNK;
        k_gather<<<(rows + 7) / 8, 256, 0, s2>>>(N, r0, rows);
        cudaEventRecord(evG[c], s2);
    }
    for (int c = 0; c < NCHUNK; c++) {
        int r0 = c * ROWS_CHUNK;
        if (r0 >= N) continue;
        int rows = (N - r0 < ROWS_CHUNK) ? (N - r0) : ROWS_CHUNK;
        int tiles = (rows + TM - 1) / TM;
        cudaStreamWaitEvent(0, evG[c], 0);
        k_tail<<<tiles, 256, SMEM_TOT>>>(bg, bo, out, N, r0);
    }
}

// round 16
// speedup vs baseline: 1.0867x; 1.0867x over previous
#include <cuda_runtime.h>
#include <cuda_bf16.h>
#include <cuda_fp16.h>
#include <math.h>
#include <stdint.h>

// ---------------------------------------------------------------------------
// GAT (4x32 heads) + autoencoder head. R16 = R15 resubmitted (prior round
// died to a container infra failure, kernel untested). R13 base (206.6us)
// with g_h stored in fp16: only consumer is k_gather's per-edge row read ->
// halves the gather's dominant L2 traffic. g_agg stays fp32.
// ---------------------------------------------------------------------------

#define MAXN 50176                    // 196 * 256
#define MAXE 800000
#define TM 64
#define KS2 264
#define SM_B (TM * KS2 * 2)
#define SMEM_TOT (SM_B + 128 * KS2 * 2)

__device__ __align__(16) __half g_h16[MAXN * 128];
__device__ __align__(16) float g_agg[MAXN * 128];
__device__ __align__(16) float g_asrc[MAXN * 4];
__device__ __align__(16) float g_adst[MAXN * 4];
__device__ __align__(16) float g_denom[MAXN * 4];
__device__ __align__(16) float g_Wcd[128 * 128];
__device__ __align__(16) float g_bcd[128];
__device__ __align__(16) __nv_bfloat16 g_BgT[128 * KS2];
__device__ __align__(16) __nv_bfloat16 g_BcdT[128 * KS2];
__device__ __align__(16) __nv_bfloat16 g_BoT[128 * KS2];
// CSR scratch
__device__ int g_cnt[MAXN];
__device__ int g_start[MAXN + 1];
__device__ int g_blk[256];
__device__ int g_srcs[MAXE];

__device__ __forceinline__ float lrelu(float v) { return v > 0.f ? v : 0.2f * v; }
__device__ __forceinline__ float elu(float v)   { return v > 0.f ? v : (expf(v) - 1.f); }
__device__ __forceinline__ float sel_head(float4 v, int lane) {
    return lane < 16 ? (lane < 8 ? v.x : v.y) : (lane < 24 ? v.z : v.w);
}

__device__ __forceinline__ uint32_t smem_u32(const void* p) {
    uint32_t a;
    asm("{ .reg .u64 t; cvta.to.shared.u64 t, %1; cvt.u32.u64 %0, t; }" : "=r"(a) : "l"(p));
    return a;
}

#define LDSM_X4(r0, r1, r2, r3, addr)                                         \
    asm volatile("ldmatrix.sync.aligned.m8n8.x4.shared.b16 {%0,%1,%2,%3}, [%4];" \
                 : "=r"(r0), "=r"(r1), "=r"(r2), "=r"(r3) : "r"(addr))
#define MMA(c, a0, a1, a2, a3, b0, b1)                                        \
    asm volatile("mma.sync.aligned.m16n8k16.row.col.f32.bf16.bf16.f32 "       \
                 "{%0,%1,%2,%3}, {%4,%5,%6,%7}, {%8,%9}, {%0,%1,%2,%3};"      \
                 : "+f"((c)[0]), "+f"((c)[1]), "+f"((c)[2]), "+f"((c)[3])     \
                 : "r"(a0), "r"(a1), "r"(a2), "r"(a3), "r"(b0), "r"(b1))

__device__ __forceinline__ void split2(char* base, int r, int k, float a, float b) {
    __nv_bfloat16 ha = __float2bfloat16(a), hb = __float2bfloat16(b);
    __nv_bfloat162 hp; hp.x = ha; hp.y = hb;
    __nv_bfloat162 lp;
    lp.x = __float2bfloat16(a - __bfloat162float(ha));
    lp.y = __float2bfloat16(b - __bfloat162float(hb));
    *(__nv_bfloat162*)(base + (size_t)(r * KS2 + k) * 2)       = hp;
    *(__nv_bfloat162*)(base + (size_t)(r * KS2 + k + 128) * 2) = lp;
}

__device__ __forceinline__ void gemm3(uint32_t sbA, uint32_t sbB,
                                      int wm, int wn, int lane, float acc[8][4]) {
    uint32_t arow = (uint32_t)(wm * 16 + (lane & 15));
    uint32_t aka  = (uint32_t)((lane >> 4) * 8);
    uint32_t brow = (uint32_t)(wn * 64 + ((lane >> 4) << 3) + (lane & 7));
    uint32_t bka  = (uint32_t)(((lane >> 3) & 1) * 8);
    #pragma unroll
    for (int p = 0; p < 3; p++) {
        int aOff = (p == 1) ? 128 : 0;
        int bOff = (p == 2) ? 128 : 0;
        uint32_t abase = sbA + (arow * KS2 + aOff + aka) * 2;
        uint32_t bbase = sbB + (brow * KS2 + bOff + bka) * 2;
        #pragma unroll
        for (int kc = 0; kc < 8; kc++) {
            uint32_t a0, a1, a2, a3;
            LDSM_X4(a0, a1, a2, a3, abase + kc * 32);
            #pragma unroll
            for (int np = 0; np < 4; np++) {
                uint32_t b0, b1, b2, b3;
                LDSM_X4(b0, b1, b2, b3, bbase + np * (16 * KS2 * 2) + kc * 32);
                MMA(acc[2 * np],     a0, a1, a2, a3, b0, b1);
                MMA(acc[2 * np + 1], a0, a1, a2, a3, b2, b3);
            }
        }
    }
}

__device__ __forceinline__ void copyB(char* smem, const __nv_bfloat16* src, int tid) {
    const float4* s4 = (const float4*)src;
    float4* d4 = (float4*)(smem + SM_B);
    #pragma unroll 4
    for (int i = tid; i < 128 * KS2 / 8; i += 256) d4[i] = s4[i];
}

// ------------------------------- CSR build ---------------------------------
__global__ void k_zero() {
    int i = blockIdx.x * 256 + threadIdx.x;
    if (i < MAXN) g_cnt[i] = 0;
}
__global__ void k_hist(const int* __restrict__ ei, int E) {
    int e = blockIdx.x * 256 + threadIdx.x;
    if (e < E) atomicAdd(&g_cnt[ei[E + e]], 1);
}
__global__ void k_scanA() {
    __shared__ int s[256];
    int i = blockIdx.x * 256 + threadIdx.x;
    s[threadIdx.x] = g_cnt[i];
    __syncthreads();
    for (int off = 128; off > 0; off >>= 1) {
        if (threadIdx.x < off) s[threadIdx.x] += s[threadIdx.x + off];
        __syncthreads();
    }
    if (threadIdx.x == 0) g_blk[blockIdx.x] = s[0];
}
__global__ void k_scanC(int nblk) {
    __shared__ int bs[256];
    __shared__ int s[256];
    int t = threadIdx.x;
    bs[t] = (t < nblk) ? g_blk[t] : 0;
    __syncthreads();
    for (int off = 1; off < 256; off <<= 1) {
        int v = (t >= off) ? bs[t - off] : 0;
        __syncthreads();
        bs[t] += v;
        __syncthreads();
    }
    int blk_off = (blockIdx.x == 0) ? 0 : bs[blockIdx.x - 1];

    int i = blockIdx.x * 256 + t;
    int c = g_cnt[i];
    s[t] = c;
    __syncthreads();
    for (int off = 1; off < 256; off <<= 1) {
        int v = (t >= off) ? s[t - off] : 0;
        __syncthreads();
        s[t] += v;
        __syncthreads();
    }
    g_start[i] = blk_off + s[t] - c;
    g_cnt[i] = 0;
    if (i == MAXN - 1) g_start[MAXN] = blk_off + s[t];
}
__global__ void k_fill(const int* __restrict__ ei, int E) {
    int e = blockIdx.x * 256 + threadIdx.x;
    if (e >= E) return;
    int d = ei[E + e];
    int pos = atomicAdd(&g_cnt[d], 1);
    g_srcs[g_start[d] + pos] = ei[e];
}

// ---------------------------------------------------------------------------
__global__ void k_prep(const float* __restrict__ We, const float* __restrict__ Wd,
                       const float* __restrict__ be, const float* __restrict__ bd) {
    int r = blockIdx.x, j = threadIdx.x;
    if (r < 128) {
        float a = 0.f;
        #pragma unroll
        for (int k = 0; k < 64; k++) a += We[r * 64 + k] * Wd[k * 128 + j];
        g_Wcd[r * 128 + j] = a;
    } else {
        float a = bd[j];
        #pragma unroll
        for (int k = 0; k < 64; k++) a += be[k] * Wd[k * 128 + j];
        g_bcd[j] = a;
    }
}

__global__ void k_prep2(const float* __restrict__ Wg, const float* __restrict__ Wo) {
    int n = blockIdx.x, k = threadIdx.x;
    float v;
    __nv_bfloat16 hb;
    v = Wg[k * 128 + n]; hb = __float2bfloat16(v);
    g_BgT[n * KS2 + k] = hb;
    g_BgT[n * KS2 + 128 + k] = __float2bfloat16(v - __bfloat162float(hb));
    v = g_Wcd[k * 128 + n]; hb = __float2bfloat16(v);
    g_BcdT[n * KS2 + k] = hb;
    g_BcdT[n * KS2 + 128 + k] = __float2bfloat16(v - __bfloat162float(hb));
    v = Wo[k * 128 + n]; hb = __float2bfloat16(v);
    g_BoT[n * KS2 + k] = hb;
    g_BoT[n * KS2 + 128 + k] = __float2bfloat16(v - __bfloat162float(hb));
}

// ---------------------------------------------------------------------------
// k1_gat: h = x @ W_gat (tensor); epilogue: logits + self-loop init of
// denom/agg; h stored fp16 (gather-only consumer).
// ---------------------------------------------------------------------------
__global__ __launch_bounds__(256, 2) void k1_gat(
    const float* __restrict__ x, const float* __restrict__ att_s,
    const float* __restrict__ att_d, int N) {
    extern __shared__ char smem[];
    uint32_t sb = smem_u32(smem);
    int tid = threadIdx.x, wid = tid >> 5, lane = tid & 31;
    int wm = wid >> 1, wn = wid & 1;
    int row0 = blockIdx.x * TM;

    const float4* x4 = (const float4*)x;
    for (int i = tid; i < TM * 32; i += 256) {
        int r = i >> 5, c4 = i & 31, gr = row0 + r;
        float4 v = (gr < N) ? x4[(size_t)gr * 32 + c4] : make_float4(0.f, 0.f, 0.f, 0.f);
        split2(smem, r, c4 * 4, v.x, v.y);
        split2(smem, r, c4 * 4 + 2, v.z, v.w);
    }
    copyB(smem, g_BgT, tid);
    __syncthreads();

    float acc[8][4];
    #pragma unroll
    for (int i = 0; i < 8; i++)
        #pragma unroll
        for (int j = 0; j < 4; j++) acc[i][j] = 0.f;
    gemm3(sb, sb + SM_B, wm, wn, lane, acc);

    int g = lane >> 2, q = lane & 3;
    int grA = row0 + wm * 16 + g;
    int grB = grA + 8;
    float pa[2], pb[2];
    #pragma unroll
    for (int hl = 0; hl < 2; hl++) {
        int hh = wn * 2 + hl;
        float sAs = 0.f, sAd = 0.f, sBs = 0.f, sBd = 0.f;
        #pragma unroll
        for (int t = 0; t < 4; t++) {
            int nt = hl * 4 + t;
            int c0 = wn * 64 + nt * 8 + q * 2;
            float w0s = __ldg(&att_s[c0]), w1s = __ldg(&att_s[c0 + 1]);
            float w0d = __ldg(&att_d[c0]), w1d = __ldg(&att_d[c0 + 1]);
            sAs += acc[nt][0] * w0s + acc[nt][1] * w1s;
            sAd += acc[nt][0] * w0d + acc[nt][1] * w1d;
            sBs += acc[nt][2] * w0s + acc[nt][3] * w1s;
            sBd += acc[nt][2] * w0d + acc[nt][3] * w1d;
        }
        #pragma unroll
        for (int off = 1; off <= 2; off <<= 1) {
            sAs += __shfl_xor_sync(0xffffffffu, sAs, off);
            sAd += __shfl_xor_sync(0xffffffffu, sAd, off);
            sBs += __shfl_xor_sync(0xffffffffu, sBs, off);
            sBd += __shfl_xor_sync(0xffffffffu, sBd, off);
        }
        pa[hl] = expf(lrelu(sAs + sAd));
        pb[hl] = expf(lrelu(sBs + sBd));
        if (q == 0) {
            if (grA < N) {
                g_asrc[grA * 4 + hh] = sAs; g_adst[grA * 4 + hh] = sAd;
                g_denom[grA * 4 + hh] = pa[hl];
            }
            if (grB < N) {
                g_asrc[grB * 4 + hh] = sBs; g_adst[grB * 4 + hh] = sBd;
                g_denom[grB * 4 + hh] = pb[hl];
            }
        }
    }
    #pragma unroll
    for (int nt = 0; nt < 8; nt++) {
        int c0 = wn * 64 + nt * 8 + q * 2;
        float pA = pa[nt >> 2], pB = pb[nt >> 2];
        if (grA < N) {
            ((__half2*)g_h16)[(size_t)grA * 64 + (c0 >> 1)] =
                __floats2half2_rn(acc[nt][0], acc[nt][1]);
            *(float2*)&g_agg[(size_t)grA * 128 + c0] =
                make_float2(pA * acc[nt][0], pA * acc[nt][1]);
        }
        if (grB < N) {
            ((__half2*)g_h16)[(size_t)grB * 64 + (c0 >> 1)] =
                __floats2half2_rn(acc[nt][2], acc[nt][3]);
            *(float2*)&g_agg[(size_t)grB * 128 + c0] =
                make_float2(pB * acc[nt][2], pB * acc[nt][3]);
        }
    }
}

// ---------------------------------------------------------------------------
// k_gather: one warp per dst node, 2-way pipelined CSR walk reading fp16 h
// (256B/row), register accumulation, single write. No atomics.
// ---------------------------------------------------------------------------
__global__ __launch_bounds__(256) void k_gather(int N) {
    int d = blockIdx.x * 8 + (threadIdx.x >> 5);
    if (d >= N) return;
    int lane = threadIdx.x & 31;

    float4 ad = ((const float4*)g_adst)[d];
    float adv = sel_head(ad, lane);

    float4 acc = ((const float4*)g_agg)[(size_t)d * 32 + lane];   // self-loop init
    float den = 0.f;

    const uint2* h2 = (const uint2*)g_h16;   // 8B = 4 halves = this lane's 4 cols
    int beg = g_start[d], end = g_start[d + 1];
    int i = beg;
    for (; i + 1 < end; i += 2) {
        int s0 = g_srcs[i], s1 = g_srcs[i + 1];
        float4 as0 = ((const float4*)g_asrc)[s0];
        float4 as1 = ((const float4*)g_asrc)[s1];
        uint2 r0 = h2[(size_t)s0 * 32 + lane];
        uint2 r1 = h2[(size_t)s1 * 32 + lane];
        float2 h0a = __half22float2(*(__half2*)&r0.x);
        float2 h0b = __half22float2(*(__half2*)&r0.y);
        float2 h1a = __half22float2(*(__half2*)&r1.x);
        float2 h1b = __half22float2(*(__half2*)&r1.y);
        float e0 = sel_head(as0, lane) + adv;
        float e1 = sel_head(as1, lane) + adv;
        float p0 = expf(e0 > 0.f ? e0 : 0.2f * e0);
        float p1 = expf(e1 > 0.f ? e1 : 0.2f * e1);
        den += p0 + p1;
        acc.x = fmaf(p0, h0a.x, fmaf(p1, h1a.x, acc.x));
        acc.y = fmaf(p0, h0a.y, fmaf(p1, h1a.y, acc.y));
        acc.z = fmaf(p0, h0b.x, fmaf(p1, h1b.x, acc.z));
        acc.w = fmaf(p0, h0b.y, fmaf(p1, h1b.y, acc.w));
    }
    if (i < end) {
        int s0 = g_srcs[i];
        float4 as0 = ((const float4*)g_asrc)[s0];
        uint2 r0 = h2[(size_t)s0 * 32 + lane];
        float2 h0a = __half22float2(*(__half2*)&r0.x);
        float2 h0b = __half22float2(*(__half2*)&r0.y);
        float e0 = sel_head(as0, lane) + adv;
        float p0 = expf(e0 > 0.f ? e0 : 0.2f * e0);
        den += p0;
        acc.x = fmaf(p0, h0a.x, acc.x);
        acc.y = fmaf(p0, h0a.y, acc.y);
        acc.z = fmaf(p0, h0b.x, acc.z);
        acc.w = fmaf(p0, h0b.y, acc.w);
    }

    ((float4*)g_agg)[(size_t)d * 32 + lane] = acc;
    if ((lane & 7) == 0)
        g_denom[d * 4 + (lane >> 3)] += den;      // add edge sum to self term
}

// ---------------------------------------------------------------------------
// k_tail: x1=elu(agg/den+bg); GEMM1 @Wcd; x2=elu(+bcd) -> A; B<-Wo^T; GEMM2.
// ---------------------------------------------------------------------------
__global__ __launch_bounds__(256, 2) void k_tail(
    const float* __restrict__ bg, const float* __restrict__ bo,
    float* __restrict__ out, int N) {
    extern __shared__ char smem[];
    uint32_t sb = smem_u32(smem);
    int tid = threadIdx.x, wid = tid >> 5, lane = tid & 31;
    int wm = wid >> 1, wn = wid & 1;
    int row0 = blockIdx.x * TM;

    const float4* agg4 = (const float4*)g_agg;
    const float4* bg4 = (const float4*)bg;
    for (int i = tid; i < TM * 32; i += 256) {
        int r = i >> 5, c4 = i & 31, gr = row0 + r;
        float4 v = make_float4(0.f, 0.f, 0.f, 0.f);
        if (gr < N) {
            float4 a = agg4[(size_t)gr * 32 + c4];
            float inv = 1.f / (g_denom[gr * 4 + (c4 >> 3)] + 1e-16f);
            float4 b = bg4[c4];
            v.x = elu(a.x * inv + b.x); v.y = elu(a.y * inv + b.y);
            v.z = elu(a.z * inv + b.z); v.w = elu(a.w * inv + b.w);
        }
        split2(smem, r, c4 * 4, v.x, v.y);
        split2(smem, r, c4 * 4 + 2, v.z, v.w);
    }
    copyB(smem, g_BcdT, tid);
    __syncthreads();

    float acc[8][4];
    #pragma unroll
    for (int i = 0; i < 8; i++)
        #pragma unroll
        for (int j = 0; j < 4; j++) acc[i][j] = 0.f;
    gemm3(sb, sb + SM_B, wm, wn, lane, acc);
    __syncthreads();

    int g = lane >> 2, q = lane & 3;
    int lrA = wm * 16 + g, lrB = lrA + 8;
    #pragma unroll
    for (int nt = 0; nt < 8; nt++) {
        int c0 = wn * 64 + nt * 8 + q * 2;
        float bc0 = g_bcd[c0], bc1 = g_bcd[c0 + 1];
        split2(smem, lrA, c0, elu(acc[nt][0] + bc0), elu(acc[nt][1] + bc1));
        split2(smem, lrB, c0, elu(acc[nt][2] + bc0), elu(acc[nt][3] + bc1));
    }
    copyB(smem, g_BoT, tid);
    __syncthreads();

    #pragma unroll
    for (int i = 0; i < 8; i++)
        #pragma unroll
        for (int j = 0; j < 4; j++) acc[i][j] = 0.f;
    gemm3(sb, sb + SM_B, wm, wn, lane, acc);

    int grA = row0 + lrA, grB = row0 + lrB;
    #pragma unroll
    for (int nt = 0; nt < 8; nt++) {
        int c0 = wn * 64 + nt * 8 + q * 2;
        float b0 = __ldg(&bo[c0]), b1 = __ldg(&bo[c0 + 1]);
        if (grA < N)
            *(float2*)&out[(size_t)grA * 128 + c0] =
                make_float2(acc[nt][0] + b0, acc[nt][1] + b1);
        if (grB < N)
            *(float2*)&out[(size_t)grB * 128 + c0] =
                make_float2(acc[nt][2] + b0, acc[nt][3] + b1);
    }
}

// ---------------------------------------------------------------------------

extern "C" void kernel_launch(void* const* d_in, const int* in_sizes, int n_in,
                              void* d_out, int out_size) {
    const float* x     = (const float*)d_in[0];
    const int*   ei    = (const int*)d_in[1];
    const float* Wg    = (const float*)d_in[2];
    const float* bg    = (const float*)d_in[3];
    const float* att_s = (const float*)d_in[4];
    const float* att_d = (const float*)d_in[5];
    const float* We    = (const float*)d_in[6];
    const float* be    = (const float*)d_in[7];
    const float* Wd    = (const float*)d_in[8];
    const float* bd    = (const float*)d_in[9];
    const float* Wo    = (const float*)d_in[10];
    const float* bo    = (const float*)d_in[11];
    float* out = (float*)d_out;

    int N = in_sizes[0] / 128;
    int E = in_sizes[1] / 2;

    // One-time resources (no device memory involved).
    static cudaStream_t s2 = nullptr;
    static cudaEvent_t evF = nullptr, evJ = nullptr;
    if (s2 == nullptr) {
        cudaStreamCreateWithFlags(&s2, cudaStreamNonBlocking);
        cudaEventCreateWithFlags(&evF, cudaEventDisableTiming);
        cudaEventCreateWithFlags(&evJ, cudaEventDisableTiming);
    }

    cudaFuncSetAttribute(k1_gat, cudaFuncAttributeMaxDynamicSharedMemorySize, SMEM_TOT);
    cudaFuncSetAttribute(k_tail, cudaFuncAttributeMaxDynamicSharedMemorySize, SMEM_TOT);

    int nb = (N + TM - 1) / TM;
    int eb = (E + 255) / 256;

    // Fork: CSR build on side stream (depends only on edge_index).
    cudaEventRecord(evF, 0);
    cudaStreamWaitEvent(s2, evF, 0);
    k_zero<<<MAXN / 256, 256, 0, s2>>>();
    k_hist<<<eb, 256, 0, s2>>>(ei, E);
    k_scanA<<<MAXN / 256, 256, 0, s2>>>();
    k_scanC<<<MAXN / 256, 256, 0, s2>>>(MAXN / 256);
    k_fill<<<eb, 256, 0, s2>>>(ei, E);
    cudaEventRecord(evJ, s2);

    // Dense prefix on the captured (default) stream.
    k_prep<<<129, 128>>>(We, Wd, be, bd);
    k_prep2<<<128, 128>>>(Wg, Wo);
    k1_gat<<<nb, 256, SMEM_TOT>>>(x, att_s, att_d, N);

    // Join: gather needs both k1_gat outputs and the CSR arrays.
    cudaStreamWaitEvent(0, evJ, 0);
    k_gather<<<(N + 7) / 8, 256>>>(N);
    k_tail<<<nb, 256, SMEM_TOT>>>(bg, bo, out, N);
}

// round 17
// speedup vs baseline: 1.1348x; 1.0443x over previous
#include <cuda_runtime.h>
#include <cuda_bf16.h>
#include <cuda_fp16.h>
#include <math.h>
#include <stdint.h>

// ---------------------------------------------------------------------------
// GAT (4x32 heads) + autoencoder head. R17 = R16 (best: 195.6us) with the
// self-loop term recomputed inside k_gather (k1_gat no longer writes
// g_agg/g_denom): -38MB of relay traffic. Everything else identical.
// ---------------------------------------------------------------------------

#define MAXN 50176                    // 196 * 256
#define MAXE 800000
#define TM 64
#define KS2 264
#define SM_B (TM * KS2 * 2)
#define SMEM_TOT (SM_B + 128 * KS2 * 2)

__device__ __align__(16) __half g_h16[MAXN * 128];
__device__ __align__(16) float g_agg[MAXN * 128];
__device__ __align__(16) float g_asrc[MAXN * 4];
__device__ __align__(16) float g_adst[MAXN * 4];
__device__ __align__(16) float g_denom[MAXN * 4];
__device__ __align__(16) float g_Wcd[128 * 128];
__device__ __align__(16) float g_bcd[128];
__device__ __align__(16) __nv_bfloat16 g_BgT[128 * KS2];
__device__ __align__(16) __nv_bfloat16 g_BcdT[128 * KS2];
__device__ __align__(16) __nv_bfloat16 g_BoT[128 * KS2];
// CSR scratch
__device__ int g_cnt[MAXN];
__device__ int g_start[MAXN + 1];
__device__ int g_blk[256];
__device__ int g_srcs[MAXE];

__device__ __forceinline__ float lrelu(float v) { return v > 0.f ? v : 0.2f * v; }
__device__ __forceinline__ float elu(float v)   { return v > 0.f ? v : (expf(v) - 1.f); }
__device__ __forceinline__ float sel_head(float4 v, int lane) {
    return lane < 16 ? (lane < 8 ? v.x : v.y) : (lane < 24 ? v.z : v.w);
}

__device__ __forceinline__ uint32_t smem_u32(const void* p) {
    uint32_t a;
    asm("{ .reg .u64 t; cvta.to.shared.u64 t, %1; cvt.u32.u64 %0, t; }" : "=r"(a) : "l"(p));
    return a;
}

#define LDSM_X4(r0, r1, r2, r3, addr)                                         \
    asm volatile("ldmatrix.sync.aligned.m8n8.x4.shared.b16 {%0,%1,%2,%3}, [%4];" \
                 : "=r"(r0), "=r"(r1), "=r"(r2), "=r"(r3) : "r"(addr))
#define MMA(c, a0, a1, a2, a3, b0, b1)                                        \
    asm volatile("mma.sync.aligned.m16n8k16.row.col.f32.bf16.bf16.f32 "       \
                 "{%0,%1,%2,%3}, {%4,%5,%6,%7}, {%8,%9}, {%0,%1,%2,%3};"      \
                 : "+f"((c)[0]), "+f"((c)[1]), "+f"((c)[2]), "+f"((c)[3])     \
                 : "r"(a0), "r"(a1), "r"(a2), "r"(a3), "r"(b0), "r"(b1))

__device__ __forceinline__ void split2(char* base, int r, int k, float a, float b) {
    __nv_bfloat16 ha = __float2bfloat16(a), hb = __float2bfloat16(b);
    __nv_bfloat162 hp; hp.x = ha; hp.y = hb;
    __nv_bfloat162 lp;
    lp.x = __float2bfloat16(a - __bfloat162float(ha));
    lp.y = __float2bfloat16(b - __bfloat162float(hb));
    *(__nv_bfloat162*)(base + (size_t)(r * KS2 + k) * 2)       = hp;
    *(__nv_bfloat162*)(base + (size_t)(r * KS2 + k + 128) * 2) = lp;
}

__device__ __forceinline__ void gemm3(uint32_t sbA, uint32_t sbB,
                                      int wm, int wn, int lane, float acc[8][4]) {
    uint32_t arow = (uint32_t)(wm * 16 + (lane & 15));
    uint32_t aka  = (uint32_t)((lane >> 4) * 8);
    uint32_t brow = (uint32_t)(wn * 64 + ((lane >> 4) << 3) + (lane & 7));
    uint32_t bka  = (uint32_t)(((lane >> 3) & 1) * 8);
    #pragma unroll
    for (int p = 0; p < 3; p++) {
        int aOff = (p == 1) ? 128 : 0;
        int bOff = (p == 2) ? 128 : 0;
        uint32_t abase = sbA + (arow * KS2 + aOff + aka) * 2;
        uint32_t bbase = sbB + (brow * KS2 + bOff + bka) * 2;
        #pragma unroll
        for (int kc = 0; kc < 8; kc++) {
            uint32_t a0, a1, a2, a3;
            LDSM_X4(a0, a1, a2, a3, abase + kc * 32);
            #pragma unroll
            for (int np = 0; np < 4; np++) {
                uint32_t b0, b1, b2, b3;
                LDSM_X4(b0, b1, b2, b3, bbase + np * (16 * KS2 * 2) + kc * 32);
                MMA(acc[2 * np],     a0, a1, a2, a3, b0, b1);
                MMA(acc[2 * np + 1], a0, a1, a2, a3, b2, b3);
            }
        }
    }
}

__device__ __forceinline__ void copyB(char* smem, const __nv_bfloat16* src, int tid) {
    const float4* s4 = (const float4*)src;
    float4* d4 = (float4*)(smem + SM_B);
    #pragma unroll 4
    for (int i = tid; i < 128 * KS2 / 8; i += 256) d4[i] = s4[i];
}

// ------------------------------- CSR build ---------------------------------
__global__ void k_zero() {
    int i = blockIdx.x * 256 + threadIdx.x;
    if (i < MAXN) g_cnt[i] = 0;
}
__global__ void k_hist(const int* __restrict__ ei, int E) {
    int e = blockIdx.x * 256 + threadIdx.x;
    if (e < E) atomicAdd(&g_cnt[ei[E + e]], 1);
}
__global__ void k_scanA() {
    __shared__ int s[256];
    int i = blockIdx.x * 256 + threadIdx.x;
    s[threadIdx.x] = g_cnt[i];
    __syncthreads();
    for (int off = 128; off > 0; off >>= 1) {
        if (threadIdx.x < off) s[threadIdx.x] += s[threadIdx.x + off];
        __syncthreads();
    }
    if (threadIdx.x == 0) g_blk[blockIdx.x] = s[0];
}
__global__ void k_scanC(int nblk) {
    __shared__ int bs[256];
    __shared__ int s[256];
    int t = threadIdx.x;
    bs[t] = (t < nblk) ? g_blk[t] : 0;
    __syncthreads();
    for (int off = 1; off < 256; off <<= 1) {
        int v = (t >= off) ? bs[t - off] : 0;
        __syncthreads();
        bs[t] += v;
        __syncthreads();
    }
    int blk_off = (blockIdx.x == 0) ? 0 : bs[blockIdx.x - 1];

    int i = blockIdx.x * 256 + t;
    int c = g_cnt[i];
    s[t] = c;
    __syncthreads();
    for (int off = 1; off < 256; off <<= 1) {
        int v = (t >= off) ? s[t - off] : 0;
        __syncthreads();
        s[t] += v;
        __syncthreads();
    }
    g_start[i] = blk_off + s[t] - c;
    g_cnt[i] = 0;
    if (i == MAXN - 1) g_start[MAXN] = blk_off + s[t];
}
__global__ void k_fill(const int* __restrict__ ei, int E) {
    int e = blockIdx.x * 256 + threadIdx.x;
    if (e >= E) return;
    int d = ei[E + e];
    int pos = atomicAdd(&g_cnt[d], 1);
    g_srcs[g_start[d] + pos] = ei[e];
}

// ---------------------------------------------------------------------------
__global__ void k_prep(const float* __restrict__ We, const float* __restrict__ Wd,
                       const float* __restrict__ be, const float* __restrict__ bd) {
    int r = blockIdx.x, j = threadIdx.x;
    if (r < 128) {
        float a = 0.f;
        #pragma unroll
        for (int k = 0; k < 64; k++) a += We[r * 64 + k] * Wd[k * 128 + j];
        g_Wcd[r * 128 + j] = a;
    } else {
        float a = bd[j];
        #pragma unroll
        for (int k = 0; k < 64; k++) a += be[k] * Wd[k * 128 + j];
        g_bcd[j] = a;
    }
}

__global__ void k_prep2(const float* __restrict__ Wg, const float* __restrict__ Wo) {
    int n = blockIdx.x, k = threadIdx.x;
    float v;
    __nv_bfloat16 hb;
    v = Wg[k * 128 + n]; hb = __float2bfloat16(v);
    g_BgT[n * KS2 + k] = hb;
    g_BgT[n * KS2 + 128 + k] = __float2bfloat16(v - __bfloat162float(hb));
    v = g_Wcd[k * 128 + n]; hb = __float2bfloat16(v);
    g_BcdT[n * KS2 + k] = hb;
    g_BcdT[n * KS2 + 128 + k] = __float2bfloat16(v - __bfloat162float(hb));
    v = Wo[k * 128 + n]; hb = __float2bfloat16(v);
    g_BoT[n * KS2 + k] = hb;
    g_BoT[n * KS2 + 128 + k] = __float2bfloat16(v - __bfloat162float(hb));
}

// ---------------------------------------------------------------------------
// k1_gat: h = x @ W_gat (tensor); epilogue: h (fp16) + logits only.
// ---------------------------------------------------------------------------
__global__ __launch_bounds__(256, 2) void k1_gat(
    const float* __restrict__ x, const float* __restrict__ att_s,
    const float* __restrict__ att_d, int N) {
    extern __shared__ char smem[];
    uint32_t sb = smem_u32(smem);
    int tid = threadIdx.x, wid = tid >> 5, lane = tid & 31;
    int wm = wid >> 1, wn = wid & 1;
    int row0 = blockIdx.x * TM;

    const float4* x4 = (const float4*)x;
    for (int i = tid; i < TM * 32; i += 256) {
        int r = i >> 5, c4 = i & 31, gr = row0 + r;
        float4 v = (gr < N) ? x4[(size_t)gr * 32 + c4] : make_float4(0.f, 0.f, 0.f, 0.f);
        split2(smem, r, c4 * 4, v.x, v.y);
        split2(smem, r, c4 * 4 + 2, v.z, v.w);
    }
    copyB(smem, g_BgT, tid);
    __syncthreads();

    float acc[8][4];
    #pragma unroll
    for (int i = 0; i < 8; i++)
        #pragma unroll
        for (int j = 0; j < 4; j++) acc[i][j] = 0.f;
    gemm3(sb, sb + SM_B, wm, wn, lane, acc);

    int g = lane >> 2, q = lane & 3;
    int grA = row0 + wm * 16 + g;
    int grB = grA + 8;
    #pragma unroll
    for (int hl = 0; hl < 2; hl++) {
        int hh = wn * 2 + hl;
        float sAs = 0.f, sAd = 0.f, sBs = 0.f, sBd = 0.f;
        #pragma unroll
        for (int t = 0; t < 4; t++) {
            int nt = hl * 4 + t;
            int c0 = wn * 64 + nt * 8 + q * 2;
            float w0s = __ldg(&att_s[c0]), w1s = __ldg(&att_s[c0 + 1]);
            float w0d = __ldg(&att_d[c0]), w1d = __ldg(&att_d[c0 + 1]);
            sAs += acc[nt][0] * w0s + acc[nt][1] * w1s;
            sAd += acc[nt][0] * w0d + acc[nt][1] * w1d;
            sBs += acc[nt][2] * w0s + acc[nt][3] * w1s;
            sBd += acc[nt][2] * w0d + acc[nt][3] * w1d;
        }
        #pragma unroll
        for (int off = 1; off <= 2; off <<= 1) {
            sAs += __shfl_xor_sync(0xffffffffu, sAs, off);
            sAd += __shfl_xor_sync(0xffffffffu, sAd, off);
            sBs += __shfl_xor_sync(0xffffffffu, sBs, off);
            sBd += __shfl_xor_sync(0xffffffffu, sBd, off);
        }
        if (q == 0) {
            if (grA < N) { g_asrc[grA * 4 + hh] = sAs; g_adst[grA * 4 + hh] = sAd; }
            if (grB < N) { g_asrc[grB * 4 + hh] = sBs; g_adst[grB * 4 + hh] = sBd; }
        }
    }
    #pragma unroll
    for (int nt = 0; nt < 8; nt++) {
        int c0 = wn * 64 + nt * 8 + q * 2;
        if (grA < N)
            ((__half2*)g_h16)[(size_t)grA * 64 + (c0 >> 1)] =
                __floats2half2_rn(acc[nt][0], acc[nt][1]);
        if (grB < N)
            ((__half2*)g_h16)[(size_t)grB * 64 + (c0 >> 1)] =
                __floats2half2_rn(acc[nt][2], acc[nt][3]);
    }
}

// ---------------------------------------------------------------------------
// k_gather: one warp per dst node; self-loop recomputed from h16[d] +
// logits; 2-way pipelined CSR walk reading fp16 h; single write. No atomics.
// ---------------------------------------------------------------------------
__global__ __launch_bounds__(256) void k_gather(int N) {
    int d = blockIdx.x * 8 + (threadIdx.x >> 5);
    if (d >= N) return;
    int lane = threadIdx.x & 31;

    float4 as_d = ((const float4*)g_asrc)[d];
    float4 ad = ((const float4*)g_adst)[d];
    float adv = sel_head(ad, lane);
    float es = sel_head(as_d, lane) + adv;            // self-loop logit
    float ps = expf(es > 0.f ? es : 0.2f * es);

    const uint2* h2 = (const uint2*)g_h16;   // 8B = 4 halves = this lane's 4 cols
    uint2 rs = h2[(size_t)d * 32 + lane];
    float2 hsa = __half22float2(*(__half2*)&rs.x);
    float2 hsb = __half22float2(*(__half2*)&rs.y);
    float4 acc = make_float4(ps * hsa.x, ps * hsa.y, ps * hsb.x, ps * hsb.y);
    float den = ps;

    int beg = g_start[d], end = g_start[d + 1];
    int i = beg;
    for (; i + 1 < end; i += 2) {
        int s0 = g_srcs[i], s1 = g_srcs[i + 1];
        float4 as0 = ((const float4*)g_asrc)[s0];
        float4 as1 = ((const float4*)g_asrc)[s1];
        uint2 r0 = h2[(size_t)s0 * 32 + lane];
        uint2 r1 = h2[(size_t)s1 * 32 + lane];
        float2 h0a = __half22float2(*(__half2*)&r0.x);
        float2 h0b = __half22float2(*(__half2*)&r0.y);
        float2 h1a = __half22float2(*(__half2*)&r1.x);
        float2 h1b = __half22float2(*(__half2*)&r1.y);
        float e0 = sel_head(as0, lane) + adv;
        float e1 = sel_head(as1, lane) + adv;
        float p0 = expf(e0 > 0.f ? e0 : 0.2f * e0);
        float p1 = expf(e1 > 0.f ? e1 : 0.2f * e1);
        den += p0 + p1;
        acc.x = fmaf(p0, h0a.x, fmaf(p1, h1a.x, acc.x));
        acc.y = fmaf(p0, h0a.y, fmaf(p1, h1a.y, acc.y));
        acc.z = fmaf(p0, h0b.x, fmaf(p1, h1b.x, acc.z));
        acc.w = fmaf(p0, h0b.y, fmaf(p1, h1b.y, acc.w));
    }
    if (i < end) {
        int s0 = g_srcs[i];
        float4 as0 = ((const float4*)g_asrc)[s0];
        uint2 r0 = h2[(size_t)s0 * 32 + lane];
        float2 h0a = __half22float2(*(__half2*)&r0.x);
        float2 h0b = __half22float2(*(__half2*)&r0.y);
        float e0 = sel_head(as0, lane) + adv;
        float p0 = expf(e0 > 0.f ? e0 : 0.2f * e0);
        den += p0;
        acc.x = fmaf(p0, h0a.x, acc.x);
        acc.y = fmaf(p0, h0a.y, acc.y);
        acc.z = fmaf(p0, h0b.x, acc.z);
        acc.w = fmaf(p0, h0b.y, acc.w);
    }

    ((float4*)g_agg)[(size_t)d * 32 + lane] = acc;
    if ((lane & 7) == 0)
        g_denom[d * 4 + (lane >> 3)] = den;
}

// ---------------------------------------------------------------------------
// k_tail: x1=elu(agg/den+bg); GEMM1 @Wcd; x2=elu(+bcd) -> A; B<-Wo^T; GEMM2.
// ---------------------------------------------------------------------------
__global__ __launch_bounds__(256, 2) void k_tail(
    const float* __restrict__ bg, const float* __restrict__ bo,
    float* __restrict__ out, int N) {
    extern __shared__ char smem[];
    uint32_t sb = smem_u32(smem);
    int tid = threadIdx.x, wid = tid >> 5, lane = tid & 31;
    int wm = wid >> 1, wn = wid & 1;
    int row0 = blockIdx.x * TM;

    const float4* agg4 = (const float4*)g_agg;
    const float4* bg4 = (const float4*)bg;
    for (int i = tid; i < TM * 32; i += 256) {
        int r = i >> 5, c4 = i & 31, gr = row0 + r;
        float4 v = make_float4(0.f, 0.f, 0.f, 0.f);
        if (gr < N) {
            float4 a = agg4[(size_t)gr * 32 + c4];
            float inv = 1.f / (g_denom[gr * 4 + (c4 >> 3)] + 1e-16f);
            float4 b = bg4[c4];
            v.x = elu(a.x * inv + b.x); v.y = elu(a.y * inv + b.y);
            v.z = elu(a.z * inv + b.z); v.w = elu(a.w * inv + b.w);
        }
        split2(smem, r, c4 * 4, v.x, v.y);
        split2(smem, r, c4 * 4 + 2, v.z, v.w);
    }
    copyB(smem, g_BcdT, tid);
    __syncthreads();

    float acc[8][4];
    #pragma unroll
    for (int i = 0; i < 8; i++)
        #pragma unroll
        for (int j = 0; j < 4; j++) acc[i][j] = 0.f;
    gemm3(sb, sb + SM_B, wm, wn, lane, acc);
    __syncthreads();

    int g = lane >> 2, q = lane & 3;
    int lrA = wm * 16 + g, lrB = lrA + 8;
    #pragma unroll
    for (int nt = 0; nt < 8; nt++) {
        int c0 = wn * 64 + nt * 8 + q * 2;
        float bc0 = g_bcd[c0], bc1 = g_bcd[c0 + 1];
        split2(smem, lrA, c0, elu(acc[nt][0] + bc0), elu(acc[nt][1] + bc1));
        split2(smem, lrB, c0, elu(acc[nt][2] + bc0), elu(acc[nt][3] + bc1));
    }
    copyB(smem, g_BoT, tid);
    __syncthreads();

    #pragma unroll
    for (int i = 0; i < 8; i++)
        #pragma unroll
        for (int j = 0; j < 4; j++) acc[i][j] = 0.f;
    gemm3(sb, sb + SM_B, wm, wn, lane, acc);

    int grA = row0 + lrA, grB = row0 + lrB;
    #pragma unroll
    for (int nt = 0; nt < 8; nt++) {
        int c0 = wn * 64 + nt * 8 + q * 2;
        float b0 = __ldg(&bo[c0]), b1 = __ldg(&bo[c0 + 1]);
        if (grA < N)
            *(float2*)&out[(size_t)grA * 128 + c0] =
                make_float2(acc[nt][0] + b0, acc[nt][1] + b1);
        if (grB < N)
            *(float2*)&out[(size_t)grB * 128 + c0] =
                make_float2(acc[nt][2] + b0, acc[nt][3] + b1);
    }
}

// ---------------------------------------------------------------------------

extern "C" void kernel_launch(void* const* d_in, const int* in_sizes, int n_in,
                              void* d_out, int out_size) {
    const float* x     = (const float*)d_in[0];
    const int*   ei    = (const int*)d_in[1];
    const float* Wg    = (const float*)d_in[2];
    const float* bg    = (const float*)d_in[3];
    const float* att_s = (const float*)d_in[4];
    const float* att_d = (const float*)d_in[5];
    const float* We    = (const float*)d_in[6];
    const float* be    = (const float*)d_in[7];
    const float* Wd    = (const float*)d_in[8];
    const float* bd    = (const float*)d_in[9];
    const float* Wo    = (const float*)d_in[10];
    const float* bo    = (const float*)d_in[11];
    float* out = (float*)d_out;

    int N = in_sizes[0] / 128;
    int E = in_sizes[1] / 2;

    // One-time resources (no device memory involved).
    static cudaStream_t s2 = nullptr;
    static cudaEvent_t evF = nullptr, evJ = nullptr;
    if (s2 == nullptr) {
        cudaStreamCreateWithFlags(&s2, cudaStreamNonBlocking);
        cudaEventCreateWithFlags(&evF, cudaEventDisableTiming);
        cudaEventCreateWithFlags(&evJ, cudaEventDisableTiming);
    }

    cudaFuncSetAttribute(k1_gat, cudaFuncAttributeMaxDynamicSharedMemorySize, SMEM_TOT);
    cudaFuncSetAttribute(k_tail, cudaFuncAttributeMaxDynamicSharedMemorySize, SMEM_TOT);

    int nb = (N + TM - 1) / TM;
    int eb = (E + 255) / 256;

    // Fork: CSR build on side stream (depends only on edge_index).
    cudaEventRecord(evF, 0);
    cudaStreamWaitEvent(s2, evF, 0);
    k_zero<<<MAXN / 256, 256, 0, s2>>>();
    k_hist<<<eb, 256, 0, s2>>>(ei, E);
    k_scanA<<<MAXN / 256, 256, 0, s2>>>();
    k_scanC<<<MAXN / 256, 256, 0, s2>>>(MAXN / 256);
    k_fill<<<eb, 256, 0, s2>>>(ei, E);
    cudaEventRecord(evJ, s2);

    // Dense prefix on the captured (default) stream.
    k_prep<<<129, 128>>>(We, Wd, be, bd);
    k_prep2<<<128, 128>>>(Wg, Wo);
    k1_gat<<<nb, 256, SMEM_TOT>>>(x, att_s, att_d, N);

    // Join: gather needs both k1_gat outputs and the CSR arrays.
    cudaStreamWaitEvent(0, evJ, 0);
    k_gather<<<(N + 7) / 8, 256>>>(N);
    k_tail<<<nb, 256, SMEM_TOT>>>(bg, bo, out, N);
}